// round 1
// baseline (speedup 1.0000x reference)
#include <cuda_runtime.h>
#include <cstddef>

// ---------------------------------------------------------------------------
// GIN (3-layer) on sm_100a.
// Per layer: agg[i] = x[i] + sum_{(j->i)} x[j]; then Linear-ReLU-Linear.
// Round 0: fp32 everywhere (exact), vectorized L2 atomics for scatter,
// 64x64x16 SIMT tiled GEMM with fused bias+ReLU epilogue.
// ---------------------------------------------------------------------------

#define N_NODES 10000
#define N_EDGES 640000
#define INC     128
#define HIDC    256

// Scratch (device globals; no allocation allowed in kernel_launch).
__device__ float g_agg[N_NODES * HIDC];
__device__ float g_hid[N_NODES * HIDC];
__device__ float g_f1 [N_NODES * HIDC];
__device__ float g_f2 [N_NODES * HIDC];

// ---------------------------------------------------------------------------
// copy: dst = src (float4 granularity). Initializes agg with the self term.
// ---------------------------------------------------------------------------
__global__ void copy_kernel(const float* __restrict__ src, float* __restrict__ dst, int n4) {
    int i = blockIdx.x * blockDim.x + threadIdx.x;
    if (i < n4) {
        reinterpret_cast<float4*>(dst)[i] =
            reinterpret_cast<const float4*>(src)[i];
    }
}

// ---------------------------------------------------------------------------
// scatter: agg[dst] += feat[src] for each edge. One warp per edge; each lane
// moves one float4 (C=128) or two (C=256). red.global.add.v4.f32 (sm_90+)
// does a no-return vectorized L2 reduction: 4x fewer atomic ops than scalar.
// ---------------------------------------------------------------------------
__global__ void __launch_bounds__(256) scatter_kernel(
    const float* __restrict__ feat, const int* __restrict__ ei,
    float* __restrict__ agg, int C4 /* = C/4 */)
{
    int e = blockIdx.x * 8 + (threadIdx.x >> 5);
    if (e >= N_EDGES) return;
    int lane = threadIdx.x & 31;
    int src = __ldg(ei + e);
    int dst = __ldg(ei + N_EDGES + e);
    const float4* fs = reinterpret_cast<const float4*>(feat) + (size_t)src * C4;
    float4*       ad = reinterpret_cast<float4*>(agg)        + (size_t)dst * C4;
    #pragma unroll 2
    for (int i = lane; i < C4; i += 32) {
        float4 v = __ldg(fs + i);
        asm volatile("red.global.add.v4.f32 [%0], {%1,%2,%3,%4};"
                     :: "l"(ad + i), "f"(v.x), "f"(v.y), "f"(v.z), "f"(v.w)
                     : "memory");
    }
}

// ---------------------------------------------------------------------------
// GEMM: C[M,N] = A[M,K] @ B[K,N] + bias (optional ReLU).
// Tile 64x64, K-step 16, 256 threads, 4x4 microtile per thread.
// Inner loop: 2x LDS.128 + 16x FFMA per k-step per thread.
// ---------------------------------------------------------------------------
__global__ void __launch_bounds__(256) gemm_bias_kernel(
    const float* __restrict__ A, const float* __restrict__ B,
    const float* __restrict__ bias, float* __restrict__ C,
    int M, int K, int N, int relu)
{
    __shared__ float As[16][68];   // [k][m], padded; 272B rows keep 16B align
    __shared__ float Bs[16][68];   // [k][n]

    const int tx = threadIdx.x & 15;
    const int ty = threadIdx.x >> 4;
    const int mb = blockIdx.y * 64;
    const int nb = blockIdx.x * 64;

    // A-tile load mapping: each thread loads one float4 along K.
    const int la_row = threadIdx.x >> 2;        // 0..63
    const int la_k   = (threadIdx.x & 3) * 4;   // 0,4,8,12
    const int arow   = mb + la_row;
    const bool a_ok  = (arow < M);

    // B-tile load mapping: each thread loads one float4 along N.
    const int lb_k = threadIdx.x >> 4;          // 0..15
    const int lb_n = (threadIdx.x & 15) * 4;    // 0..60

    float acc[4][4] = {};

    for (int k0 = 0; k0 < K; k0 += 16) {
        float4 av = a_ok
            ? *reinterpret_cast<const float4*>(A + (size_t)arow * K + k0 + la_k)
            : make_float4(0.f, 0.f, 0.f, 0.f);
        float4 bv = *reinterpret_cast<const float4*>(
            B + (size_t)(k0 + lb_k) * N + nb + lb_n);

        As[la_k + 0][la_row] = av.x;
        As[la_k + 1][la_row] = av.y;
        As[la_k + 2][la_row] = av.z;
        As[la_k + 3][la_row] = av.w;
        *reinterpret_cast<float4*>(&Bs[lb_k][lb_n]) = bv;
        __syncthreads();

        #pragma unroll
        for (int kk = 0; kk < 16; kk++) {
            float4 a4 = *reinterpret_cast<const float4*>(&As[kk][ty * 4]);
            float4 b4 = *reinterpret_cast<const float4*>(&Bs[kk][tx * 4]);
            acc[0][0] += a4.x * b4.x; acc[0][1] += a4.x * b4.y;
            acc[0][2] += a4.x * b4.z; acc[0][3] += a4.x * b4.w;
            acc[1][0] += a4.y * b4.x; acc[1][1] += a4.y * b4.y;
            acc[1][2] += a4.y * b4.z; acc[1][3] += a4.y * b4.w;
            acc[2][0] += a4.z * b4.x; acc[2][1] += a4.z * b4.y;
            acc[2][2] += a4.z * b4.z; acc[2][3] += a4.z * b4.w;
            acc[3][0] += a4.w * b4.x; acc[3][1] += a4.w * b4.y;
            acc[3][2] += a4.w * b4.z; acc[3][3] += a4.w * b4.w;
        }
        __syncthreads();
    }

    float4 bb = *reinterpret_cast<const float4*>(bias + nb + tx * 4);
    #pragma unroll
    for (int i = 0; i < 4; i++) {
        int row = mb + ty * 4 + i;
        if (row < M) {
            float4 o;
            o.x = acc[i][0] + bb.x;
            o.y = acc[i][1] + bb.y;
            o.z = acc[i][2] + bb.z;
            o.w = acc[i][3] + bb.w;
            if (relu) {
                o.x = fmaxf(o.x, 0.f); o.y = fmaxf(o.y, 0.f);
                o.z = fmaxf(o.z, 0.f); o.w = fmaxf(o.w, 0.f);
            }
            *reinterpret_cast<float4*>(C + (size_t)row * N + nb + tx * 4) = o;
        }
    }
}

// ---------------------------------------------------------------------------
// Host launch
// ---------------------------------------------------------------------------
static void launch_layer(const float* feat, int C, const int* ei,
                         const float* Wa, const float* ba,
                         const float* Wb, const float* bb,
                         float* agg, float* hid, float* out, int out_relu)
{
    // agg = feat (self term)
    int n4 = N_NODES * C / 4;
    copy_kernel<<<(n4 + 255) / 256, 256>>>(feat, agg, n4);

    // agg += scatter(feat)
    scatter_kernel<<<N_EDGES / 8, 256>>>(feat, ei, agg, C / 4);

    // hid = relu(agg @ Wa + ba)
    dim3 g1(HIDC / 64, (N_NODES + 63) / 64);
    gemm_bias_kernel<<<g1, 256>>>(agg, Wa, ba, hid, N_NODES, C, HIDC, 1);

    // out = hid @ Wb + bb  (+ inter-layer ReLU for layers 0,1)
    dim3 g2(HIDC / 64, (N_NODES + 63) / 64);
    gemm_bias_kernel<<<g2, 256>>>(hid, Wb, bb, out, N_NODES, HIDC, HIDC, out_relu);
}

extern "C" void kernel_launch(void* const* d_in, const int* in_sizes, int n_in,
                              void* d_out, int out_size)
{
    const float* x   = (const float*)d_in[0];
    const int*   ei  = (const int*)  d_in[1];
    const float* W0a = (const float*)d_in[2];
    const float* b0a = (const float*)d_in[3];
    const float* W0b = (const float*)d_in[4];
    const float* b0b = (const float*)d_in[5];
    const float* W1a = (const float*)d_in[6];
    const float* b1a = (const float*)d_in[7];
    const float* W1b = (const float*)d_in[8];
    const float* b1b = (const float*)d_in[9];
    const float* W2a = (const float*)d_in[10];
    const float* b2a = (const float*)d_in[11];
    const float* W2b = (const float*)d_in[12];
    const float* b2b = (const float*)d_in[13];

    float *agg, *hid, *f1, *f2;
    cudaGetSymbolAddress((void**)&agg, g_agg);
    cudaGetSymbolAddress((void**)&hid, g_hid);
    cudaGetSymbolAddress((void**)&f1,  g_f1);
    cudaGetSymbolAddress((void**)&f2,  g_f2);

    // Layer 0: C=128 -> f1 (with inter-layer ReLU)
    launch_layer(x,  INC,  ei, W0a, b0a, W0b, b0b, agg, hid, f1, 1);
    // Layer 1: C=256 -> f2 (with inter-layer ReLU)
    launch_layer(f1, HIDC, ei, W1a, b1a, W1b, b1b, agg, hid, f2, 1);
    // Layer 2: C=256 -> d_out (no final ReLU)
    launch_layer(f2, HIDC, ei, W2a, b2a, W2b, b2b, agg, hid, (float*)d_out, 0);
}

// round 3
// speedup vs baseline: 2.0071x; 2.0071x over previous
#include <cuda_runtime.h>
#include <cstdint>
#include <cstddef>

// ---------------------------------------------------------------------------
// GIN (3-layer) — Round 3.
// GEMM: mma.sync tf32 (HMMA), cp.async double-buffered.
// Aggregation: per-launch CSR build + warp-per-node gather (no atomics),
// self-term fused.
// ---------------------------------------------------------------------------

#define N_NODES 10000
#define N_EDGES 640000
#define INC     128
#define HIDC    256

__device__ float g_agg[N_NODES * HIDC];
__device__ float g_hid[N_NODES * HIDC];
__device__ float g_f1 [N_NODES * HIDC];
__device__ float g_f2 [N_NODES * HIDC];
__device__ float g_wt [6 * HIDC * HIDC];
__device__ int   g_deg[N_NODES];
__device__ int   g_off[N_NODES + 1];
__device__ int   g_cur[N_NODES];
__device__ int   g_eid[N_EDGES];

// ---------------------------------------------------------------------------
__device__ __forceinline__ uint32_t smem_u32(const void* p) {
    uint32_t a;
    asm("{ .reg .u64 t; cvta.to.shared.u64 t, %1; cvt.u32.u64 %0, t; }" : "=r"(a) : "l"(p));
    return a;
}
__device__ __forceinline__ float tf32r(float v) {
    uint32_t r;
    asm("cvt.rna.tf32.f32 %0, %1;" : "=r"(r) : "f"(v));
    return __uint_as_float(r);
}
__device__ __forceinline__ void cp16(uint32_t saddr, const void* g, int sz) {
    asm volatile("cp.async.cg.shared.global [%0], [%1], 16, %2;"
                 :: "r"(saddr), "l"(g), "r"(sz) : "memory");
}
__device__ __forceinline__ void cp_commit() {
    asm volatile("cp.async.commit_group;" ::: "memory");
}
template <int N>
__device__ __forceinline__ void cp_wait() {
    asm volatile("cp.async.wait_group %0;" :: "n"(N) : "memory");
}
__device__ __forceinline__ void mma_tf32(float* c, uint32_t a0, uint32_t a1,
                                         uint32_t a2, uint32_t a3,
                                         uint32_t b0, uint32_t b1) {
    asm volatile(
        "mma.sync.aligned.m16n8k8.row.col.f32.tf32.tf32.f32 "
        "{%0,%1,%2,%3}, {%4,%5,%6,%7}, {%8,%9}, {%0,%1,%2,%3};"
        : "+f"(c[0]), "+f"(c[1]), "+f"(c[2]), "+f"(c[3])
        : "r"(a0), "r"(a1), "r"(a2), "r"(a3), "r"(b0), "r"(b1));
}

// ---------------------------------------------------------------------------
// CSR build
// ---------------------------------------------------------------------------
__global__ void zero_deg_kernel() {
    int i = blockIdx.x * blockDim.x + threadIdx.x;
    if (i < N_NODES) g_deg[i] = 0;
}
__global__ void count_kernel(const int* __restrict__ ei) {
    int e = blockIdx.x * blockDim.x + threadIdx.x;
    if (e < N_EDGES) atomicAdd(&g_deg[__ldg(ei + N_EDGES + e)], 1);
}
__global__ void __launch_bounds__(1024) scan_kernel() {
    __shared__ int part[1024];
    const int t = threadIdx.x;
    const int CH = 10;  // 1024*10 >= 10000
    int local[CH];
    int base = t * CH, s = 0;
    #pragma unroll
    for (int k = 0; k < CH; k++) {
        int idx = base + k;
        local[k] = (idx < N_NODES) ? g_deg[idx] : 0;
        s += local[k];
    }
    part[t] = s;
    __syncthreads();
    for (int d = 1; d < 1024; d <<= 1) {
        int v = (t >= d) ? part[t - d] : 0;
        __syncthreads();
        part[t] += v;
        __syncthreads();
    }
    int run = (t > 0) ? part[t - 1] : 0;
    #pragma unroll
    for (int k = 0; k < CH; k++) {
        int idx = base + k;
        if (idx < N_NODES) {
            g_off[idx] = run;
            g_cur[idx] = run;
            run += local[k];
        }
    }
    if (t == 1023) g_off[N_NODES] = part[1023];
}
__global__ void fill_kernel(const int* __restrict__ ei) {
    int e = blockIdx.x * blockDim.x + threadIdx.x;
    if (e < N_EDGES) {
        int d = __ldg(ei + N_EDGES + e);
        int pos = atomicAdd(&g_cur[d], 1);
        g_eid[pos] = __ldg(ei + e);
    }
}

// ---------------------------------------------------------------------------
// gather: agg[i] = feat[i] + sum_{j in nbrs(i)} feat[j]   (warp per node)
// ---------------------------------------------------------------------------
__global__ void __launch_bounds__(256) gather_kernel(
    const float* __restrict__ feat, float* __restrict__ agg, int C4)
{
    int w = (blockIdx.x * blockDim.x + threadIdx.x) >> 5;
    if (w >= N_NODES) return;
    int lane = threadIdx.x & 31;
    int beg = __ldg(g_off + w), end = __ldg(g_off + w + 1);
    const float4* f = reinterpret_cast<const float4*>(feat);

    if (C4 == 32) {
        float4 a = __ldg(f + (size_t)w * 32 + lane);
        int j = beg;
        for (; j + 1 < end; j += 2) {
            int s0 = __ldg(g_eid + j), s1 = __ldg(g_eid + j + 1);
            float4 v0 = __ldg(f + (size_t)s0 * 32 + lane);
            float4 v1 = __ldg(f + (size_t)s1 * 32 + lane);
            a.x += v0.x + v1.x; a.y += v0.y + v1.y;
            a.z += v0.z + v1.z; a.w += v0.w + v1.w;
        }
        if (j < end) {
            int s0 = __ldg(g_eid + j);
            float4 v0 = __ldg(f + (size_t)s0 * 32 + lane);
            a.x += v0.x; a.y += v0.y; a.z += v0.z; a.w += v0.w;
        }
        reinterpret_cast<float4*>(agg)[(size_t)w * 32 + lane] = a;
    } else {
        float4 a0 = __ldg(f + (size_t)w * 64 + lane);
        float4 a1 = __ldg(f + (size_t)w * 64 + lane + 32);
        int j = beg;
        for (; j + 1 < end; j += 2) {
            int s0 = __ldg(g_eid + j), s1 = __ldg(g_eid + j + 1);
            const float4* p0 = f + (size_t)s0 * 64;
            const float4* p1 = f + (size_t)s1 * 64;
            float4 u0 = __ldg(p0 + lane), u1 = __ldg(p0 + lane + 32);
            float4 v0 = __ldg(p1 + lane), v1 = __ldg(p1 + lane + 32);
            a0.x += u0.x + v0.x; a0.y += u0.y + v0.y;
            a0.z += u0.z + v0.z; a0.w += u0.w + v0.w;
            a1.x += u1.x + v1.x; a1.y += u1.y + v1.y;
            a1.z += u1.z + v1.z; a1.w += u1.w + v1.w;
        }
        if (j < end) {
            int s0 = __ldg(g_eid + j);
            const float4* p0 = f + (size_t)s0 * 64;
            float4 u0 = __ldg(p0 + lane), u1 = __ldg(p0 + lane + 32);
            a0.x += u0.x; a0.y += u0.y; a0.z += u0.z; a0.w += u0.w;
            a1.x += u1.x; a1.y += u1.y; a1.z += u1.z; a1.w += u1.w;
        }
        reinterpret_cast<float4*>(agg)[(size_t)w * 64 + lane] = a0;
        reinterpret_cast<float4*>(agg)[(size_t)w * 64 + lane + 32] = a1;
    }
}

// ---------------------------------------------------------------------------
// transpose + tf32-round: Wt[n*K + k] = tf32(W[k*256 + n])
// ---------------------------------------------------------------------------
__global__ void transpose_w(const float* __restrict__ W, float* __restrict__ Wt, int K) {
    int idx = blockIdx.x * 256 + threadIdx.x;
    if (idx < 256 * K) {
        int n = idx / K, k = idx - n * K;
        Wt[idx] = tf32r(__ldg(W + k * 256 + n));
    }
}

// ---------------------------------------------------------------------------
// GEMM: C[M,256] = A[M,K] @ Wt^T (+bias, opt ReLU). mma.sync tf32.
// CTA tile 128x128xK16, 8 warps (4M x 2N), warp tile 32x64.
// ---------------------------------------------------------------------------
#define BM 128
#define BN 128
#define BK 16
#define LDT 20          // padded row stride (floats)
#define TBYTES (BM * LDT * 4)

__global__ void __launch_bounds__(256) gemm_mma(
    const float* __restrict__ A, const float* __restrict__ Bt,
    const float* __restrict__ bias, float* __restrict__ C,
    int M, int K, int relu)
{
    __shared__ __align__(16) float sm[4 * BM * LDT];
    float* As[2] = { sm,            sm + BM * LDT };
    float* Bs[2] = { sm + 2*BM*LDT, sm + 3*BM*LDT };
    const uint32_t sbase = smem_u32(sm);

    const int tid = threadIdx.x;
    const int lane = tid & 31, wid = tid >> 5;
    const int warp_m = wid & 3, warp_n = wid >> 2;
    const int g = lane >> 2, tig = lane & 3;
    const int nb = blockIdx.x * BN;
    const int mb = blockIdx.y * BM;

    const int lr  = tid >> 2;          // 0..63  (row base per thread pair)
    const int lc4 = tid & 3;           // 0..3

    float acc[2][8][4];
    #pragma unroll
    for (int mt = 0; mt < 2; mt++)
        #pragma unroll
        for (int nt = 0; nt < 8; nt++)
            #pragma unroll
            for (int q = 0; q < 4; q++) acc[mt][nt][q] = 0.f;

    const int NC = K >> 4;

    // issue chunk into buffer `buf`
    auto issue = [&](int buf, int k0) {
        #pragma unroll
        for (int t = 0; t < 2; t++) {
            int r = lr + t * 64;
            int grow = mb + r;
            int rowc = grow < M ? grow : M - 1;
            const float* gp = A + (size_t)rowc * K + k0 + lc4 * 4;
            uint32_t sa = sbase + buf * TBYTES + (r * LDT + lc4 * 4) * 4;
            cp16(sa, gp, grow < M ? 16 : 0);
        }
        #pragma unroll
        for (int t = 0; t < 2; t++) {
            int r = lr + t * 64;
            const float* gp = Bt + (size_t)(nb + r) * K + k0 + lc4 * 4;
            uint32_t sa = sbase + (2 + buf) * TBYTES + (r * LDT + lc4 * 4) * 4;
            cp16(sa, gp, 16);
        }
        cp_commit();
    };

    issue(0, 0);

    for (int i = 0; i < NC; i++) {
        if (i + 1 < NC) issue((i + 1) & 1, (i + 1) << 4);
        if (i + 1 < NC) cp_wait<1>(); else cp_wait<0>();
        __syncthreads();

        const float* as = As[i & 1];
        const float* bs = Bs[i & 1];

        #pragma unroll
        for (int k8 = 0; k8 < 2; k8++) {
            const int kb = k8 * 8;
            uint32_t af[2][4];
            #pragma unroll
            for (int mt = 0; mt < 2; mt++) {
                int rb = warp_m * 32 + mt * 16;
                af[mt][0] = __float_as_uint(tf32r(as[(rb + g)     * LDT + kb + tig]));
                af[mt][1] = __float_as_uint(tf32r(as[(rb + 8 + g) * LDT + kb + tig]));
                af[mt][2] = __float_as_uint(tf32r(as[(rb + g)     * LDT + kb + tig + 4]));
                af[mt][3] = __float_as_uint(tf32r(as[(rb + 8 + g) * LDT + kb + tig + 4]));
            }
            #pragma unroll
            for (int nt = 0; nt < 8; nt++) {
                int cb = warp_n * 64 + nt * 8;
                uint32_t b0 = __float_as_uint(bs[(cb + g) * LDT + kb + tig]);
                uint32_t b1 = __float_as_uint(bs[(cb + g) * LDT + kb + tig + 4]);
                #pragma unroll
                for (int mt = 0; mt < 2; mt++)
                    mma_tf32(acc[mt][nt], af[mt][0], af[mt][1], af[mt][2], af[mt][3], b0, b1);
            }
        }
        __syncthreads();
    }

    // Epilogue: bias + optional ReLU, float2 stores.
    #pragma unroll
    for (int nt = 0; nt < 8; nt++) {
        int col = nb + warp_n * 64 + nt * 8 + 2 * tig;
        float2 bv = __ldg(reinterpret_cast<const float2*>(bias + col));
        #pragma unroll
        for (int mt = 0; mt < 2; mt++) {
            int row0 = mb + warp_m * 32 + mt * 16 + g;
            float2 o0 = make_float2(acc[mt][nt][0] + bv.x, acc[mt][nt][1] + bv.y);
            float2 o1 = make_float2(acc[mt][nt][2] + bv.x, acc[mt][nt][3] + bv.y);
            if (relu) {
                o0.x = fmaxf(o0.x, 0.f); o0.y = fmaxf(o0.y, 0.f);
                o1.x = fmaxf(o1.x, 0.f); o1.y = fmaxf(o1.y, 0.f);
            }
            if (row0 < M)
                *reinterpret_cast<float2*>(C + (size_t)row0 * 256 + col) = o0;
            if (row0 + 8 < M)
                *reinterpret_cast<float2*>(C + (size_t)(row0 + 8) * 256 + col) = o1;
        }
    }
}

// ---------------------------------------------------------------------------
static void launch_layer(const float* feat, int C,
                         const float* Wta, const float* ba,
                         const float* Wtb, const float* bb,
                         float* agg, float* hid, float* out, int out_relu)
{
    gather_kernel<<<(N_NODES * 32 + 255) / 256, 256>>>(feat, agg, C / 4);
    dim3 grid(256 / BN, (N_NODES + BM - 1) / BM);
    gemm_mma<<<grid, 256>>>(agg, Wta, ba, hid, N_NODES, C, 1);
    gemm_mma<<<grid, 256>>>(hid, Wtb, bb, out, N_NODES, HIDC, out_relu);
}

extern "C" void kernel_launch(void* const* d_in, const int* in_sizes, int n_in,
                              void* d_out, int out_size)
{
    const float* x  = (const float*)d_in[0];
    const int*   ei = (const int*)  d_in[1];
    const float* W[6]  = { (const float*)d_in[2],  (const float*)d_in[4],
                           (const float*)d_in[6],  (const float*)d_in[8],
                           (const float*)d_in[10], (const float*)d_in[12] };
    const float* bv[6] = { (const float*)d_in[3],  (const float*)d_in[5],
                           (const float*)d_in[7],  (const float*)d_in[9],
                           (const float*)d_in[11], (const float*)d_in[13] };
    const int Kw[6] = { INC, HIDC, HIDC, HIDC, HIDC, HIDC };

    float *agg, *hid, *f1, *f2, *wt;
    cudaGetSymbolAddress((void**)&agg, g_agg);
    cudaGetSymbolAddress((void**)&hid, g_hid);
    cudaGetSymbolAddress((void**)&f1,  g_f1);
    cudaGetSymbolAddress((void**)&f2,  g_f2);
    cudaGetSymbolAddress((void**)&wt,  g_wt);

    // CSR build (once per launch; reused by all 3 layers)
    zero_deg_kernel<<<(N_NODES + 255) / 256, 256>>>();
    count_kernel<<<(N_EDGES + 255) / 256, 256>>>(ei);
    scan_kernel<<<1, 1024>>>();
    fill_kernel<<<(N_EDGES + 255) / 256, 256>>>(ei);

    // Weight transpose + tf32 rounding
    float* Wt[6];
    for (int i = 0; i < 6; i++) {
        Wt[i] = wt + i * HIDC * HIDC;
        int tot = 256 * Kw[i];
        transpose_w<<<(tot + 255) / 256, 256>>>(W[i], Wt[i], Kw[i]);
    }

    launch_layer(x,  INC,  Wt[0], bv[0], Wt[1], bv[1], agg, hid, f1, 1);
    launch_layer(f1, HIDC, Wt[2], bv[2], Wt[3], bv[3], agg, hid, f2, 1);
    launch_layer(f2, HIDC, Wt[4], bv[4], Wt[5], bv[5], agg, hid, (float*)d_out, 0);
}

// round 4
// speedup vs baseline: 2.0189x; 1.0059x over previous
#include <cuda_runtime.h>
#include <cstdint>
#include <cstddef>

// ---------------------------------------------------------------------------
// GIN (3-layer) — Round 4.
// GEMM: mma.sync tf32 (HMMA), cp.async double-buffered (unchanged from R3).
// CSR build: 4-edge ILP count/fill. Single merged transpose kernel.
// Gather: 4-edge unrolled warp-per-node.
// ---------------------------------------------------------------------------

#define N_NODES 10000
#define N_EDGES 640000
#define INC     128
#define HIDC    256

__device__ float g_agg[N_NODES * HIDC];
__device__ float g_hid[N_NODES * HIDC];
__device__ float g_f1 [N_NODES * HIDC];
__device__ float g_f2 [N_NODES * HIDC];
__device__ float g_wt [6 * HIDC * HIDC];
__device__ int   g_deg[N_NODES];
__device__ int   g_off[N_NODES + 1];
__device__ int   g_cur[N_NODES];
__device__ int   g_eid[N_EDGES];

// ---------------------------------------------------------------------------
__device__ __forceinline__ uint32_t smem_u32(const void* p) {
    uint32_t a;
    asm("{ .reg .u64 t; cvta.to.shared.u64 t, %1; cvt.u32.u64 %0, t; }" : "=r"(a) : "l"(p));
    return a;
}
__device__ __forceinline__ float tf32r(float v) {
    uint32_t r;
    asm("cvt.rna.tf32.f32 %0, %1;" : "=r"(r) : "f"(v));
    return __uint_as_float(r);
}
__device__ __forceinline__ void cp16(uint32_t saddr, const void* g, int sz) {
    asm volatile("cp.async.cg.shared.global [%0], [%1], 16, %2;"
                 :: "r"(saddr), "l"(g), "r"(sz) : "memory");
}
__device__ __forceinline__ void cp_commit() {
    asm volatile("cp.async.commit_group;" ::: "memory");
}
template <int N>
__device__ __forceinline__ void cp_wait() {
    asm volatile("cp.async.wait_group %0;" :: "n"(N) : "memory");
}
__device__ __forceinline__ void mma_tf32(float* c, uint32_t a0, uint32_t a1,
                                         uint32_t a2, uint32_t a3,
                                         uint32_t b0, uint32_t b1) {
    asm volatile(
        "mma.sync.aligned.m16n8k8.row.col.f32.tf32.tf32.f32 "
        "{%0,%1,%2,%3}, {%4,%5,%6,%7}, {%8,%9}, {%0,%1,%2,%3};"
        : "+f"(c[0]), "+f"(c[1]), "+f"(c[2]), "+f"(c[3])
        : "r"(a0), "r"(a1), "r"(a2), "r"(a3), "r"(b0), "r"(b1));
}

// ---------------------------------------------------------------------------
// CSR build
// ---------------------------------------------------------------------------
__global__ void zero_deg_kernel() {
    int i = blockIdx.x * blockDim.x + threadIdx.x;
    if (i < N_NODES) g_deg[i] = 0;
}
// 4 edges per thread (int4 loads) for memory-level parallelism.
__global__ void __launch_bounds__(256) count_kernel(const int* __restrict__ ei) {
    int base = (blockIdx.x * blockDim.x + threadIdx.x) * 4;
    if (base >= N_EDGES) return;
    int4 d = *reinterpret_cast<const int4*>(ei + N_EDGES + base);
    atomicAdd(&g_deg[d.x], 1);
    atomicAdd(&g_deg[d.y], 1);
    atomicAdd(&g_deg[d.z], 1);
    atomicAdd(&g_deg[d.w], 1);
}
__global__ void __launch_bounds__(1024) scan_kernel() {
    __shared__ int part[1024];
    const int t = threadIdx.x;
    const int CH = 10;  // 1024*10 >= 10000
    int local[CH];
    int base = t * CH, s = 0;
    #pragma unroll
    for (int k = 0; k < CH; k++) {
        int idx = base + k;
        local[k] = (idx < N_NODES) ? g_deg[idx] : 0;
        s += local[k];
    }
    part[t] = s;
    __syncthreads();
    for (int d = 1; d < 1024; d <<= 1) {
        int v = (t >= d) ? part[t - d] : 0;
        __syncthreads();
        part[t] += v;
        __syncthreads();
    }
    int run = (t > 0) ? part[t - 1] : 0;
    #pragma unroll
    for (int k = 0; k < CH; k++) {
        int idx = base + k;
        if (idx < N_NODES) {
            g_off[idx] = run;
            g_cur[idx] = run;
            run += local[k];
        }
    }
    if (t == 1023) g_off[N_NODES] = part[1023];
}
__global__ void __launch_bounds__(256) fill_kernel(const int* __restrict__ ei) {
    int base = (blockIdx.x * blockDim.x + threadIdx.x) * 4;
    if (base >= N_EDGES) return;
    int4 s = *reinterpret_cast<const int4*>(ei + base);
    int4 d = *reinterpret_cast<const int4*>(ei + N_EDGES + base);
    int p0 = atomicAdd(&g_cur[d.x], 1);
    int p1 = atomicAdd(&g_cur[d.y], 1);
    int p2 = atomicAdd(&g_cur[d.z], 1);
    int p3 = atomicAdd(&g_cur[d.w], 1);
    g_eid[p0] = s.x;
    g_eid[p1] = s.y;
    g_eid[p2] = s.z;
    g_eid[p3] = s.w;
}

// ---------------------------------------------------------------------------
// gather: agg[i] = feat[i] + sum_{j in nbrs(i)} feat[j]   (warp per node,
// 4 edges in flight per iteration)
// ---------------------------------------------------------------------------
__global__ void __launch_bounds__(256) gather_kernel(
    const float* __restrict__ feat, float* __restrict__ agg, int C4)
{
    int w = (blockIdx.x * blockDim.x + threadIdx.x) >> 5;
    if (w >= N_NODES) return;
    int lane = threadIdx.x & 31;
    int beg = __ldg(g_off + w), end = __ldg(g_off + w + 1);
    const float4* f = reinterpret_cast<const float4*>(feat);

    if (C4 == 32) {
        float4 a = __ldg(f + (size_t)w * 32 + lane);
        int j = beg;
        for (; j + 3 < end; j += 4) {
            int s0 = __ldg(g_eid + j),     s1 = __ldg(g_eid + j + 1);
            int s2 = __ldg(g_eid + j + 2), s3 = __ldg(g_eid + j + 3);
            float4 v0 = __ldg(f + (size_t)s0 * 32 + lane);
            float4 v1 = __ldg(f + (size_t)s1 * 32 + lane);
            float4 v2 = __ldg(f + (size_t)s2 * 32 + lane);
            float4 v3 = __ldg(f + (size_t)s3 * 32 + lane);
            a.x += (v0.x + v1.x) + (v2.x + v3.x);
            a.y += (v0.y + v1.y) + (v2.y + v3.y);
            a.z += (v0.z + v1.z) + (v2.z + v3.z);
            a.w += (v0.w + v1.w) + (v2.w + v3.w);
        }
        for (; j < end; j++) {
            int s0 = __ldg(g_eid + j);
            float4 v0 = __ldg(f + (size_t)s0 * 32 + lane);
            a.x += v0.x; a.y += v0.y; a.z += v0.z; a.w += v0.w;
        }
        reinterpret_cast<float4*>(agg)[(size_t)w * 32 + lane] = a;
    } else {
        float4 a0 = __ldg(f + (size_t)w * 64 + lane);
        float4 a1 = __ldg(f + (size_t)w * 64 + lane + 32);
        int j = beg;
        for (; j + 3 < end; j += 4) {
            int s0 = __ldg(g_eid + j),     s1 = __ldg(g_eid + j + 1);
            int s2 = __ldg(g_eid + j + 2), s3 = __ldg(g_eid + j + 3);
            const float4* p0 = f + (size_t)s0 * 64;
            const float4* p1 = f + (size_t)s1 * 64;
            const float4* p2 = f + (size_t)s2 * 64;
            const float4* p3 = f + (size_t)s3 * 64;
            float4 u0 = __ldg(p0 + lane), w0 = __ldg(p0 + lane + 32);
            float4 u1 = __ldg(p1 + lane), w1 = __ldg(p1 + lane + 32);
            float4 u2 = __ldg(p2 + lane), w2 = __ldg(p2 + lane + 32);
            float4 u3 = __ldg(p3 + lane), w3 = __ldg(p3 + lane + 32);
            a0.x += (u0.x + u1.x) + (u2.x + u3.x);
            a0.y += (u0.y + u1.y) + (u2.y + u3.y);
            a0.z += (u0.z + u1.z) + (u2.z + u3.z);
            a0.w += (u0.w + u1.w) + (u2.w + u3.w);
            a1.x += (w0.x + w1.x) + (w2.x + w3.x);
            a1.y += (w0.y + w1.y) + (w2.y + w3.y);
            a1.z += (w0.z + w1.z) + (w2.z + w3.z);
            a1.w += (w0.w + w1.w) + (w2.w + w3.w);
        }
        for (; j < end; j++) {
            int s0 = __ldg(g_eid + j);
            const float4* p0 = f + (size_t)s0 * 64;
            float4 u0 = __ldg(p0 + lane), w0 = __ldg(p0 + lane + 32);
            a0.x += u0.x; a0.y += u0.y; a0.z += u0.z; a0.w += u0.w;
            a1.x += w0.x; a1.y += w0.y; a1.z += w0.z; a1.w += w0.w;
        }
        reinterpret_cast<float4*>(agg)[(size_t)w * 64 + lane] = a0;
        reinterpret_cast<float4*>(agg)[(size_t)w * 64 + lane + 32] = a1;
    }
}

// ---------------------------------------------------------------------------
// Merged transpose + tf32-round for all 6 weight matrices.
// Layout in g_wt: slot i at i*HIDC*HIDC, Wt[n*K + k] = tf32(W[k*256 + n]).
// ---------------------------------------------------------------------------
__global__ void __launch_bounds__(256) transpose_all(
    const float* __restrict__ W0, const float* __restrict__ W1,
    const float* __restrict__ W2, const float* __restrict__ W3,
    const float* __restrict__ W4, const float* __restrict__ W5,
    float* __restrict__ wt)
{
    // total: 256*128 (slot0) + 5 * 256*256
    int idx = blockIdx.x * 256 + threadIdx.x;
    const int S0 = 256 * INC;
    const int S = 256 * HIDC;
    const float* W; int K; int loc; float* out;
    if (idx < S0) { W = W0; K = INC; loc = idx; out = wt; }
    else {
        int r = idx - S0;
        int slot = r / S; loc = r - slot * S; K = HIDC;
        const float* Ws[5] = { W1, W2, W3, W4, W5 };
        if (slot >= 5) return;
        W = Ws[slot]; out = wt + (slot + 1) * HIDC * HIDC;
    }
    int n = loc / K, k = loc - n * K;
    out[(size_t)n * K + k] = tf32r(__ldg(W + (size_t)k * 256 + n));
}

// ---------------------------------------------------------------------------
// GEMM: C[M,256] = A[M,K] @ Wt^T (+bias, opt ReLU). mma.sync tf32.
// CTA tile 128x128xK16, 8 warps (4M x 2N), warp tile 32x64.
// ---------------------------------------------------------------------------
#define BM 128
#define BN 128
#define BK 16
#define LDT 20
#define TBYTES (BM * LDT * 4)

__global__ void __launch_bounds__(256) gemm_mma(
    const float* __restrict__ A, const float* __restrict__ Bt,
    const float* __restrict__ bias, float* __restrict__ C,
    int M, int K, int relu)
{
    __shared__ __align__(16) float sm[4 * BM * LDT];
    float* As[2] = { sm,            sm + BM * LDT };
    float* Bs[2] = { sm + 2*BM*LDT, sm + 3*BM*LDT };
    const uint32_t sbase = smem_u32(sm);

    const int tid = threadIdx.x;
    const int lane = tid & 31, wid = tid >> 5;
    const int warp_m = wid & 3, warp_n = wid >> 2;
    const int g = lane >> 2, tig = lane & 3;
    const int nb = blockIdx.x * BN;
    const int mb = blockIdx.y * BM;

    const int lr  = tid >> 2;
    const int lc4 = tid & 3;

    float acc[2][8][4];
    #pragma unroll
    for (int mt = 0; mt < 2; mt++)
        #pragma unroll
        for (int nt = 0; nt < 8; nt++)
            #pragma unroll
            for (int q = 0; q < 4; q++) acc[mt][nt][q] = 0.f;

    const int NC = K >> 4;

    auto issue = [&](int buf, int k0) {
        #pragma unroll
        for (int t = 0; t < 2; t++) {
            int r = lr + t * 64;
            int grow = mb + r;
            int rowc = grow < M ? grow : M - 1;
            const float* gp = A + (size_t)rowc * K + k0 + lc4 * 4;
            uint32_t sa = sbase + buf * TBYTES + (r * LDT + lc4 * 4) * 4;
            cp16(sa, gp, grow < M ? 16 : 0);
        }
        #pragma unroll
        for (int t = 0; t < 2; t++) {
            int r = lr + t * 64;
            const float* gp = Bt + (size_t)(nb + r) * K + k0 + lc4 * 4;
            uint32_t sa = sbase + (2 + buf) * TBYTES + (r * LDT + lc4 * 4) * 4;
            cp16(sa, gp, 16);
        }
        cp_commit();
    };

    issue(0, 0);

    for (int i = 0; i < NC; i++) {
        if (i + 1 < NC) issue((i + 1) & 1, (i + 1) << 4);
        if (i + 1 < NC) cp_wait<1>(); else cp_wait<0>();
        __syncthreads();

        const float* as = As[i & 1];
        const float* bs = Bs[i & 1];

        #pragma unroll
        for (int k8 = 0; k8 < 2; k8++) {
            const int kb = k8 * 8;
            uint32_t af[2][4];
            #pragma unroll
            for (int mt = 0; mt < 2; mt++) {
                int rb = warp_m * 32 + mt * 16;
                af[mt][0] = __float_as_uint(tf32r(as[(rb + g)     * LDT + kb + tig]));
                af[mt][1] = __float_as_uint(tf32r(as[(rb + 8 + g) * LDT + kb + tig]));
                af[mt][2] = __float_as_uint(tf32r(as[(rb + g)     * LDT + kb + tig + 4]));
                af[mt][3] = __float_as_uint(tf32r(as[(rb + 8 + g) * LDT + kb + tig + 4]));
            }
            #pragma unroll
            for (int nt = 0; nt < 8; nt++) {
                int cb = warp_n * 64 + nt * 8;
                uint32_t b0 = __float_as_uint(bs[(cb + g) * LDT + kb + tig]);
                uint32_t b1 = __float_as_uint(bs[(cb + g) * LDT + kb + tig + 4]);
                #pragma unroll
                for (int mt = 0; mt < 2; mt++)
                    mma_tf32(acc[mt][nt], af[mt][0], af[mt][1], af[mt][2], af[mt][3], b0, b1);
            }
        }
        __syncthreads();
    }

    #pragma unroll
    for (int nt = 0; nt < 8; nt++) {
        int col = nb + warp_n * 64 + nt * 8 + 2 * tig;
        float2 bv = __ldg(reinterpret_cast<const float2*>(bias + col));
        #pragma unroll
        for (int mt = 0; mt < 2; mt++) {
            int row0 = mb + warp_m * 32 + mt * 16 + g;
            float2 o0 = make_float2(acc[mt][nt][0] + bv.x, acc[mt][nt][1] + bv.y);
            float2 o1 = make_float2(acc[mt][nt][2] + bv.x, acc[mt][nt][3] + bv.y);
            if (relu) {
                o0.x = fmaxf(o0.x, 0.f); o0.y = fmaxf(o0.y, 0.f);
                o1.x = fmaxf(o1.x, 0.f); o1.y = fmaxf(o1.y, 0.f);
            }
            if (row0 < M)
                *reinterpret_cast<float2*>(C + (size_t)row0 * 256 + col) = o0;
            if (row0 + 8 < M)
                *reinterpret_cast<float2*>(C + (size_t)(row0 + 8) * 256 + col) = o1;
        }
    }
}

// ---------------------------------------------------------------------------
static void launch_layer(const float* feat, int C,
                         const float* Wta, const float* ba,
                         const float* Wtb, const float* bb,
                         float* agg, float* hid, float* out, int out_relu)
{
    gather_kernel<<<(N_NODES * 32 + 255) / 256, 256>>>(feat, agg, C / 4);
    dim3 grid(256 / BN, (N_NODES + BM - 1) / BM);
    gemm_mma<<<grid, 256>>>(agg, Wta, ba, hid, N_NODES, C, 1);
    gemm_mma<<<grid, 256>>>(hid, Wtb, bb, out, N_NODES, HIDC, out_relu);
}

extern "C" void kernel_launch(void* const* d_in, const int* in_sizes, int n_in,
                              void* d_out, int out_size)
{
    const float* x  = (const float*)d_in[0];
    const int*   ei = (const int*)  d_in[1];

    float *agg, *hid, *f1, *f2, *wt;
    cudaGetSymbolAddress((void**)&agg, g_agg);
    cudaGetSymbolAddress((void**)&hid, g_hid);
    cudaGetSymbolAddress((void**)&f1,  g_f1);
    cudaGetSymbolAddress((void**)&f2,  g_f2);
    cudaGetSymbolAddress((void**)&wt,  g_wt);

    // CSR build (reused by all 3 layers)
    zero_deg_kernel<<<(N_NODES + 255) / 256, 256>>>();
    count_kernel<<<(N_EDGES / 4 + 255) / 256, 256>>>(ei);
    scan_kernel<<<1, 1024>>>();
    fill_kernel<<<(N_EDGES / 4 + 255) / 256, 256>>>(ei);

    // All weight transposes in one launch
    {
        int tot = 256 * INC + 5 * 256 * HIDC;
        transpose_all<<<(tot + 255) / 256, 256>>>(
            (const float*)d_in[2], (const float*)d_in[4], (const float*)d_in[6],
            (const float*)d_in[8], (const float*)d_in[10], (const float*)d_in[12], wt);
    }
    float* Wt[6];
    for (int i = 0; i < 6; i++) Wt[i] = wt + i * HIDC * HIDC;
    const float* bv[6] = { (const float*)d_in[3],  (const float*)d_in[5],
                           (const float*)d_in[7],  (const float*)d_in[9],
                           (const float*)d_in[11], (const float*)d_in[13] };

    launch_layer(x,  INC,  Wt[0], bv[0], Wt[1], bv[1], agg, hid, f1, 1);
    launch_layer(f1, HIDC, Wt[2], bv[2], Wt[3], bv[3], agg, hid, f2, 1);
    launch_layer(f2, HIDC, Wt[4], bv[4], Wt[5], bv[5], agg, hid, (float*)d_out, 0);
}

// round 5
// speedup vs baseline: 2.2460x; 1.1125x over previous
#include <cuda_runtime.h>
#include <cstdint>
#include <cstddef>

// ---------------------------------------------------------------------------
// GIN (3-layer) — Round 5.
// CSR: memset + fused(count&rank + weight transpose) + scan + atomic-free fill.
// GEMM: mma.sync tf32, BM=64/BN=128 (314 CTAs, fluid occupancy).
// Gather: warp-per-node (unchanged).
// ---------------------------------------------------------------------------

#define N_NODES 10000
#define N_EDGES 640000
#define INC     128
#define HIDC    256

__device__ float g_agg[N_NODES * HIDC];
__device__ float g_hid[N_NODES * HIDC];
__device__ float g_f1 [N_NODES * HIDC];
__device__ float g_f2 [N_NODES * HIDC];
__device__ float g_wt [6 * HIDC * HIDC];
__device__ int   g_deg[N_NODES];
__device__ int   g_off[N_NODES + 1];
__device__ int   g_rank[N_EDGES];
__device__ int   g_eid[N_EDGES];

// ---------------------------------------------------------------------------
__device__ __forceinline__ uint32_t smem_u32(const void* p) {
    uint32_t a;
    asm("{ .reg .u64 t; cvta.to.shared.u64 t, %1; cvt.u32.u64 %0, t; }" : "=r"(a) : "l"(p));
    return a;
}
__device__ __forceinline__ float tf32r(float v) {
    uint32_t r;
    asm("cvt.rna.tf32.f32 %0, %1;" : "=r"(r) : "f"(v));
    return __uint_as_float(r);
}
__device__ __forceinline__ void cp16(uint32_t saddr, const void* g, int sz) {
    asm volatile("cp.async.cg.shared.global [%0], [%1], 16, %2;"
                 :: "r"(saddr), "l"(g), "r"(sz) : "memory");
}
__device__ __forceinline__ void cp_commit() {
    asm volatile("cp.async.commit_group;" ::: "memory");
}
template <int N>
__device__ __forceinline__ void cp_wait() {
    asm volatile("cp.async.wait_group %0;" :: "n"(N) : "memory");
}
__device__ __forceinline__ void mma_tf32(float* c, uint32_t a0, uint32_t a1,
                                         uint32_t a2, uint32_t a3,
                                         uint32_t b0, uint32_t b1) {
    asm volatile(
        "mma.sync.aligned.m16n8k8.row.col.f32.tf32.tf32.f32 "
        "{%0,%1,%2,%3}, {%4,%5,%6,%7}, {%8,%9}, {%0,%1,%2,%3};"
        : "+f"(c[0]), "+f"(c[1]), "+f"(c[2]), "+f"(c[3])
        : "r"(a0), "r"(a1), "r"(a2), "r"(a3), "r"(b0), "r"(b1));
}

// ---------------------------------------------------------------------------
// Fused kernel: blocks [0, CNT_BLKS) do degree count + per-edge rank;
// blocks [CNT_BLKS, ...) do weight transpose + tf32 rounding.
// ---------------------------------------------------------------------------
#define CNT_BLKS 625   // 625 * 256 * 4 = 640000 edges
#define TW_ELEMS (256 * INC + 5 * 256 * HIDC)
#define TW_BLKS  ((TW_ELEMS + 255) / 256)

__global__ void __launch_bounds__(256) count_and_transpose(
    const int* __restrict__ ei,
    const float* __restrict__ W0, const float* __restrict__ W1,
    const float* __restrict__ W2, const float* __restrict__ W3,
    const float* __restrict__ W4, const float* __restrict__ W5,
    float* __restrict__ wt)
{
    int b = blockIdx.x;
    if (b < CNT_BLKS) {
        int base = (b * 256 + threadIdx.x) * 4;
        if (base >= N_EDGES) return;
        int4 d = *reinterpret_cast<const int4*>(ei + N_EDGES + base);
        int r0 = atomicAdd(&g_deg[d.x], 1);
        int r1 = atomicAdd(&g_deg[d.y], 1);
        int r2 = atomicAdd(&g_deg[d.z], 1);
        int r3 = atomicAdd(&g_deg[d.w], 1);
        *reinterpret_cast<int4*>(g_rank + base) = make_int4(r0, r1, r2, r3);
    } else {
        int idx = (b - CNT_BLKS) * 256 + threadIdx.x;
        const int S0 = 256 * INC;
        const int S = 256 * HIDC;
        const float* W; int K; int loc; float* out;
        if (idx < S0) { W = W0; K = INC; loc = idx; out = wt; }
        else {
            int r = idx - S0;
            int slot = r / S; loc = r - slot * S; K = HIDC;
            if (slot >= 5) return;
            const float* Ws[5] = { W1, W2, W3, W4, W5 };
            W = Ws[slot]; out = wt + (slot + 1) * HIDC * HIDC;
        }
        int n = loc / K, k = loc - n * K;
        out[(size_t)n * K + k] = tf32r(__ldg(W + (size_t)k * 256 + n));
    }
}

__global__ void __launch_bounds__(1024) scan_kernel() {
    __shared__ int part[1024];
    const int t = threadIdx.x;
    const int CH = 10;
    int local[CH];
    int base = t * CH, s = 0;
    #pragma unroll
    for (int k = 0; k < CH; k++) {
        int idx = base + k;
        local[k] = (idx < N_NODES) ? g_deg[idx] : 0;
        s += local[k];
    }
    part[t] = s;
    __syncthreads();
    for (int d = 1; d < 1024; d <<= 1) {
        int v = (t >= d) ? part[t - d] : 0;
        __syncthreads();
        part[t] += v;
        __syncthreads();
    }
    int run = (t > 0) ? part[t - 1] : 0;
    #pragma unroll
    for (int k = 0; k < CH; k++) {
        int idx = base + k;
        if (idx < N_NODES) { g_off[idx] = run; run += local[k]; }
    }
    if (t == 1023) g_off[N_NODES] = part[1023];
}

// Atomic-free fill: eid[off[dst] + rank] = src.
__global__ void __launch_bounds__(256) fill_kernel(const int* __restrict__ ei) {
    int base = (blockIdx.x * blockDim.x + threadIdx.x) * 4;
    if (base >= N_EDGES) return;
    int4 s = *reinterpret_cast<const int4*>(ei + base);
    int4 d = *reinterpret_cast<const int4*>(ei + N_EDGES + base);
    int4 r = *reinterpret_cast<const int4*>(g_rank + base);
    g_eid[__ldg(g_off + d.x) + r.x] = s.x;
    g_eid[__ldg(g_off + d.y) + r.y] = s.y;
    g_eid[__ldg(g_off + d.z) + r.z] = s.z;
    g_eid[__ldg(g_off + d.w) + r.w] = s.w;
}

// ---------------------------------------------------------------------------
// gather: agg[i] = feat[i] + sum_{j in nbrs(i)} feat[j]   (warp per node)
// ---------------------------------------------------------------------------
__global__ void __launch_bounds__(256) gather_kernel(
    const float* __restrict__ feat, float* __restrict__ agg, int C4)
{
    int w = (blockIdx.x * blockDim.x + threadIdx.x) >> 5;
    if (w >= N_NODES) return;
    int lane = threadIdx.x & 31;
    int beg = __ldg(g_off + w), end = __ldg(g_off + w + 1);
    const float4* f = reinterpret_cast<const float4*>(feat);

    if (C4 == 32) {
        float4 a = __ldg(f + (size_t)w * 32 + lane);
        int j = beg;
        for (; j + 3 < end; j += 4) {
            int s0 = __ldg(g_eid + j),     s1 = __ldg(g_eid + j + 1);
            int s2 = __ldg(g_eid + j + 2), s3 = __ldg(g_eid + j + 3);
            float4 v0 = __ldg(f + (size_t)s0 * 32 + lane);
            float4 v1 = __ldg(f + (size_t)s1 * 32 + lane);
            float4 v2 = __ldg(f + (size_t)s2 * 32 + lane);
            float4 v3 = __ldg(f + (size_t)s3 * 32 + lane);
            a.x += (v0.x + v1.x) + (v2.x + v3.x);
            a.y += (v0.y + v1.y) + (v2.y + v3.y);
            a.z += (v0.z + v1.z) + (v2.z + v3.z);
            a.w += (v0.w + v1.w) + (v2.w + v3.w);
        }
        for (; j < end; j++) {
            int s0 = __ldg(g_eid + j);
            float4 v0 = __ldg(f + (size_t)s0 * 32 + lane);
            a.x += v0.x; a.y += v0.y; a.z += v0.z; a.w += v0.w;
        }
        reinterpret_cast<float4*>(agg)[(size_t)w * 32 + lane] = a;
    } else {
        float4 a0 = __ldg(f + (size_t)w * 64 + lane);
        float4 a1 = __ldg(f + (size_t)w * 64 + lane + 32);
        int j = beg;
        for (; j + 3 < end; j += 4) {
            int s0 = __ldg(g_eid + j),     s1 = __ldg(g_eid + j + 1);
            int s2 = __ldg(g_eid + j + 2), s3 = __ldg(g_eid + j + 3);
            const float4* p0 = f + (size_t)s0 * 64;
            const float4* p1 = f + (size_t)s1 * 64;
            const float4* p2 = f + (size_t)s2 * 64;
            const float4* p3 = f + (size_t)s3 * 64;
            float4 u0 = __ldg(p0 + lane), w0 = __ldg(p0 + lane + 32);
            float4 u1 = __ldg(p1 + lane), w1 = __ldg(p1 + lane + 32);
            float4 u2 = __ldg(p2 + lane), w2 = __ldg(p2 + lane + 32);
            float4 u3 = __ldg(p3 + lane), w3 = __ldg(p3 + lane + 32);
            a0.x += (u0.x + u1.x) + (u2.x + u3.x);
            a0.y += (u0.y + u1.y) + (u2.y + u3.y);
            a0.z += (u0.z + u1.z) + (u2.z + u3.z);
            a0.w += (u0.w + u1.w) + (u2.w + u3.w);
            a1.x += (w0.x + w1.x) + (w2.x + w3.x);
            a1.y += (w0.y + w1.y) + (w2.y + w3.y);
            a1.z += (w0.z + w1.z) + (w2.z + w3.z);
            a1.w += (w0.w + w1.w) + (w2.w + w3.w);
        }
        for (; j < end; j++) {
            int s0 = __ldg(g_eid + j);
            const float4* p0 = f + (size_t)s0 * 64;
            float4 u0 = __ldg(p0 + lane), w0 = __ldg(p0 + lane + 32);
            a0.x += u0.x; a0.y += u0.y; a0.z += u0.z; a0.w += u0.w;
            a1.x += w0.x; a1.y += w0.y; a1.z += w0.z; a1.w += w0.w;
        }
        reinterpret_cast<float4*>(agg)[(size_t)w * 64 + lane] = a0;
        reinterpret_cast<float4*>(agg)[(size_t)w * 64 + lane + 32] = a1;
    }
}

// ---------------------------------------------------------------------------
// GEMM: C[M,256] = A[M,K] @ Wt^T (+bias, opt ReLU). mma.sync tf32.
// CTA tile 64x128xK16, 8 warps (2M x 4N), warp tile 32x32.
// ---------------------------------------------------------------------------
#define BM 64
#define BN 128
#define LDT 20
#define ATB (BM * LDT * 4)
#define BTB (BN * LDT * 4)

__global__ void __launch_bounds__(256) gemm_mma(
    const float* __restrict__ A, const float* __restrict__ Bt,
    const float* __restrict__ bias, float* __restrict__ C,
    int M, int K, int relu)
{
    __shared__ __align__(16) float sm[2 * (BM + BN) * LDT];
    float* As[2] = { sm,                 sm + BM * LDT };
    float* Bs[2] = { sm + 2 * BM * LDT,  sm + 2 * BM * LDT + BN * LDT };
    const uint32_t sa_base = smem_u32(sm);
    const uint32_t sb_base = sa_base + 2 * ATB;

    const int tid = threadIdx.x;
    const int lane = tid & 31, wid = tid >> 5;
    const int warp_m = wid & 1, warp_n = wid >> 1;
    const int g = lane >> 2, tig = lane & 3;
    const int nb = blockIdx.x * BN;
    const int mb = blockIdx.y * BM;

    const int lr  = tid >> 2;          // 0..63
    const int lc4 = tid & 3;           // 0..3

    float acc[2][4][4];
    #pragma unroll
    for (int mt = 0; mt < 2; mt++)
        #pragma unroll
        for (int nt = 0; nt < 4; nt++)
            #pragma unroll
            for (int q = 0; q < 4; q++) acc[mt][nt][q] = 0.f;

    const int NC = K >> 4;

    auto issue = [&](int buf, int k0) {
        {   // A: 64 rows, one float4 per thread
            int grow = mb + lr;
            int rowc = grow < M ? grow : M - 1;
            const float* gp = A + (size_t)rowc * K + k0 + lc4 * 4;
            uint32_t sa = sa_base + buf * ATB + (lr * LDT + lc4 * 4) * 4;
            cp16(sa, gp, grow < M ? 16 : 0);
        }
        #pragma unroll
        for (int t = 0; t < 2; t++) {  // B: 128 rows, two float4 per thread
            int r = lr + t * 64;
            const float* gp = Bt + (size_t)(nb + r) * K + k0 + lc4 * 4;
            uint32_t sa = sb_base + buf * BTB + (r * LDT + lc4 * 4) * 4;
            cp16(sa, gp, 16);
        }
        cp_commit();
    };

    issue(0, 0);

    for (int i = 0; i < NC; i++) {
        if (i + 1 < NC) issue((i + 1) & 1, (i + 1) << 4);
        if (i + 1 < NC) cp_wait<1>(); else cp_wait<0>();
        __syncthreads();

        const float* as = As[i & 1];
        const float* bs = Bs[i & 1];

        #pragma unroll
        for (int k8 = 0; k8 < 2; k8++) {
            const int kb = k8 * 8;
            uint32_t af[2][4];
            #pragma unroll
            for (int mt = 0; mt < 2; mt++) {
                int rb = warp_m * 32 + mt * 16;
                af[mt][0] = __float_as_uint(tf32r(as[(rb + g)     * LDT + kb + tig]));
                af[mt][1] = __float_as_uint(tf32r(as[(rb + 8 + g) * LDT + kb + tig]));
                af[mt][2] = __float_as_uint(tf32r(as[(rb + g)     * LDT + kb + tig + 4]));
                af[mt][3] = __float_as_uint(tf32r(as[(rb + 8 + g) * LDT + kb + tig + 4]));
            }
            #pragma unroll
            for (int nt = 0; nt < 4; nt++) {
                int cb = warp_n * 32 + nt * 8;
                uint32_t b0 = __float_as_uint(bs[(cb + g) * LDT + kb + tig]);
                uint32_t b1 = __float_as_uint(bs[(cb + g) * LDT + kb + tig + 4]);
                #pragma unroll
                for (int mt = 0; mt < 2; mt++)
                    mma_tf32(acc[mt][nt], af[mt][0], af[mt][1], af[mt][2], af[mt][3], b0, b1);
            }
        }
        __syncthreads();
    }

    #pragma unroll
    for (int nt = 0; nt < 4; nt++) {
        int col = nb + warp_n * 32 + nt * 8 + 2 * tig;
        float2 bv = __ldg(reinterpret_cast<const float2*>(bias + col));
        #pragma unroll
        for (int mt = 0; mt < 2; mt++) {
            int row0 = mb + warp_m * 32 + mt * 16 + g;
            float2 o0 = make_float2(acc[mt][nt][0] + bv.x, acc[mt][nt][1] + bv.y);
            float2 o1 = make_float2(acc[mt][nt][2] + bv.x, acc[mt][nt][3] + bv.y);
            if (relu) {
                o0.x = fmaxf(o0.x, 0.f); o0.y = fmaxf(o0.y, 0.f);
                o1.x = fmaxf(o1.x, 0.f); o1.y = fmaxf(o1.y, 0.f);
            }
            if (row0 < M)
                *reinterpret_cast<float2*>(C + (size_t)row0 * 256 + col) = o0;
            if (row0 + 8 < M)
                *reinterpret_cast<float2*>(C + (size_t)(row0 + 8) * 256 + col) = o1;
        }
    }
}

// ---------------------------------------------------------------------------
static void launch_layer(const float* feat, int C,
                         const float* Wta, const float* ba,
                         const float* Wtb, const float* bb,
                         float* agg, float* hid, float* out, int out_relu)
{
    gather_kernel<<<(N_NODES * 32 + 255) / 256, 256>>>(feat, agg, C / 4);
    dim3 grid(256 / BN, (N_NODES + BM - 1) / BM);
    gemm_mma<<<grid, 256>>>(agg, Wta, ba, hid, N_NODES, C, 1);
    gemm_mma<<<grid, 256>>>(hid, Wtb, bb, out, N_NODES, HIDC, out_relu);
}

extern "C" void kernel_launch(void* const* d_in, const int* in_sizes, int n_in,
                              void* d_out, int out_size)
{
    const float* x  = (const float*)d_in[0];
    const int*   ei = (const int*)  d_in[1];

    float *agg, *hid, *f1, *f2, *wt;
    int* degp;
    cudaGetSymbolAddress((void**)&agg, g_agg);
    cudaGetSymbolAddress((void**)&hid, g_hid);
    cudaGetSymbolAddress((void**)&f1,  g_f1);
    cudaGetSymbolAddress((void**)&f2,  g_f2);
    cudaGetSymbolAddress((void**)&wt,  g_wt);
    cudaGetSymbolAddress((void**)&degp, g_deg);

    cudaMemsetAsync(degp, 0, N_NODES * sizeof(int));

    // count+rank (+ fused weight transpose), scan, atomic-free fill
    count_and_transpose<<<CNT_BLKS + TW_BLKS, 256>>>(
        ei,
        (const float*)d_in[2], (const float*)d_in[4], (const float*)d_in[6],
        (const float*)d_in[8], (const float*)d_in[10], (const float*)d_in[12], wt);
    scan_kernel<<<1, 1024>>>();
    fill_kernel<<<(N_EDGES / 4 + 255) / 256, 256>>>(ei);

    float* Wt[6];
    for (int i = 0; i < 6; i++) Wt[i] = wt + i * HIDC * HIDC;
    const float* bv[6] = { (const float*)d_in[3],  (const float*)d_in[5],
                           (const float*)d_in[7],  (const float*)d_in[9],
                           (const float*)d_in[11], (const float*)d_in[13] };

    launch_layer(x,  INC,  Wt[0], bv[0], Wt[1], bv[1], agg, hid, f1, 1);
    launch_layer(f1, HIDC, Wt[2], bv[2], Wt[3], bv[3], agg, hid, f2, 1);
    launch_layer(f2, HIDC, Wt[4], bv[4], Wt[5], bv[5], agg, hid, (float*)d_out, 0);
}